// round 15
// baseline (speedup 1.0000x reference)
#include <cuda_runtime.h>
#include <cstdint>

#define NN 100000
#define NE 1600000
#define CD 128

static const int BM = 64;
static const int TILES = (NN + BM - 1) / BM;   // 1563
static const int AST = 132;                    // row-major A stride (4r+k bank spread)
static const int SMEM_FLOATS = (CD*CD*2 + BM*AST*2 + 64);
static const int SMEM_BYTES = SMEM_FLOATS * 4; // 198912 bytes
static const int SCAN_BLKS = (NN + 255) / 256; // 391

// ---- scratch (device globals: allocation-free rule) ----
__device__ float g_agg[(size_t)NN * CD];
__device__ float g_h[(size_t)NN * CD];
__device__ int   g_csrc[NE + 8];               // +8 pad: aligned-window overread safety
__device__ int   g_rowptr[NN];
__device__ int   g_cursor[NN];
__device__ int   g_cnt[NN];
__device__ int   g_part[SCAN_BLKS];
__device__ float g_stats[4];
__device__ int   g_is64;
__device__ int   g_ticket;

// ---------------- packed f32x2 helpers ----------------
__device__ __forceinline__ unsigned long long pk2(float lo, float hi) {
    unsigned long long r;
    asm("mov.b64 %0, {%1, %2};" : "=l"(r) : "f"(lo), "f"(hi));
    return r;
}
__device__ __forceinline__ void fma2(unsigned long long& d,
                                     unsigned long long a, unsigned long long b) {
    asm("fma.rn.f32x2 %0, %1, %2, %0;" : "+l"(d) : "l"(a), "l"(b));
}
__device__ __forceinline__ void upk2(unsigned long long v, float& lo, float& hi) {
    asm("mov.b64 {%0, %1}, %2;" : "=f"(lo), "=f"(hi) : "l"(v));
}

// ---------------- init: zero counts + stats + ticket, detect edge dtype ----------------
__global__ void k_init(const long long* __restrict__ ei) {
    int i = blockIdx.x * blockDim.x + threadIdx.x;
    if (i < NN) g_cnt[i] = 0;
    if (i < 4)  g_stats[i] = 0.f;
    if (i == 0) {
        g_ticket = 0;
        // int64 vs int32: int32 data read as int64 carries a node-id in the
        // high word (value >= NN w.h.p. within 16 samples); true int64 < NN.
        int ok = 1;
        for (int j = 0; j < 16; ++j) {
            unsigned long long v = (unsigned long long)ei[j];
            if (v >= (unsigned long long)NN) ok = 0;
        }
        g_is64 = ok;
    }
}

// ---------------- in-degree count ----------------
__global__ void k_count(const void* __restrict__ eiv) {
    int i = blockIdx.x * blockDim.x + threadIdx.x;
    if (i >= NE) return;
    int d;
    if (g_is64) d = (int)((const long long*)eiv)[NE + i];
    else        d = ((const int*)eiv)[NE + i];
    atomicAdd(&g_cnt[d], 1);
}

// ---------------- CSR build: block-local exclusive scan ----------------
__global__ void k_scan1() {
    __shared__ int s[256];
    int b = blockIdx.x, tid = threadIdx.x;
    int i = b * 256 + tid;
    int v = (i < NN) ? g_cnt[i] : 0;
    s[tid] = v;
    __syncthreads();
    #pragma unroll
    for (int off = 1; off < 256; off <<= 1) {
        int t = (tid >= off) ? s[tid - off] : 0;
        __syncthreads();
        s[tid] += t;
        __syncthreads();
    }
    if (i < NN) g_rowptr[i] = s[tid] - v;     // exclusive within block
    if (tid == 255) g_part[b] = s[255];
}

// parallel exclusive scan of the 391 block partials (one block, 512 threads)
__global__ void k_scan2() {
    __shared__ int s[512];
    int tid = threadIdx.x;
    int v = (tid < SCAN_BLKS) ? g_part[tid] : 0;
    s[tid] = v;
    __syncthreads();
    #pragma unroll
    for (int off = 1; off < 512; off <<= 1) {
        int t = (tid >= off) ? s[tid - off] : 0;
        __syncthreads();
        s[tid] += t;
        __syncthreads();
    }
    if (tid < SCAN_BLKS) g_part[tid] = s[tid] - v;   // exclusive
}

__global__ void k_scan3() {
    int i = blockIdx.x * blockDim.x + threadIdx.x;
    if (i >= NN) return;
    int r = g_rowptr[i] + g_part[i >> 8];
    g_rowptr[i] = r;
    g_cursor[i] = r;
}

__global__ void k_fill(const void* __restrict__ eiv) {
    int i = blockIdx.x * blockDim.x + threadIdx.x;
    if (i >= NE) return;
    int s, d;
    if (g_is64) {
        const long long* ei = (const long long*)eiv;
        s = (int)ei[i]; d = (int)ei[NE + i];
    } else {
        const int* ei = (const int*)eiv;
        s = ei[i]; d = ei[NE + i];
    }
    int pos = atomicAdd(&g_cursor[d], 1);
    g_csrc[pos] = s;
}

// ---------------- pull-side mean aggregation: one warp per dst node ----------------
// Aligned int4 index windows. Head/tail windows carry predicates; interior
// windows are guard-free and unrolled x2 (up to 10 loads in flight/warp).
// Also resets the GEMM work-stealing ticket (stream-ordered before each k_gemm).
__global__ void k_agg(const float* __restrict__ featExt) {
    if (blockIdx.x == 0 && threadIdx.x == 0) g_ticket = 0;
    int w = (blockIdx.x * blockDim.x + threadIdx.x) >> 5;
    int lane = threadIdx.x & 31;
    if (w >= NN) return;
    const float* feat = featExt ? featExt : g_h;
    const int base = g_rowptr[w];
    const int deg = g_cnt[w];
    const int end = base + deg;

    float4 a0 = make_float4(0.f, 0.f, 0.f, 0.f);
    float4 a1 = a0, a2 = a0, a3 = a0;

    int wpos = base & ~3;

    // head window (predicated) — only if base is misaligned
    if (wpos < base) {
        int4 q = __ldg((const int4*)&g_csrc[wpos]);
        if (wpos + 0 >= base && wpos + 0 < end) {
            float4 v = ((const float4*)(feat + (size_t)q.x * CD))[lane];
            a0.x += v.x; a0.y += v.y; a0.z += v.z; a0.w += v.w;
        }
        if (wpos + 1 >= base && wpos + 1 < end) {
            float4 v = ((const float4*)(feat + (size_t)q.y * CD))[lane];
            a1.x += v.x; a1.y += v.y; a1.z += v.z; a1.w += v.w;
        }
        if (wpos + 2 >= base && wpos + 2 < end) {
            float4 v = ((const float4*)(feat + (size_t)q.z * CD))[lane];
            a2.x += v.x; a2.y += v.y; a2.z += v.z; a2.w += v.w;
        }
        if (wpos + 3 >= base && wpos + 3 < end) {
            float4 v = ((const float4*)(feat + (size_t)q.w * CD))[lane];
            a3.x += v.x; a3.y += v.y; a3.z += v.z; a3.w += v.w;
        }
        wpos += 4;
    }

    // interior windows — fully covered, no guards; unroll x2 for deeper MLP
    #pragma unroll 2
    for (; wpos + 4 <= end; wpos += 4) {
        int4 q = __ldg((const int4*)&g_csrc[wpos]);
        float4 v0 = ((const float4*)(feat + (size_t)q.x * CD))[lane];
        float4 v1 = ((const float4*)(feat + (size_t)q.y * CD))[lane];
        float4 v2 = ((const float4*)(feat + (size_t)q.z * CD))[lane];
        float4 v3 = ((const float4*)(feat + (size_t)q.w * CD))[lane];
        a0.x += v0.x; a0.y += v0.y; a0.z += v0.z; a0.w += v0.w;
        a1.x += v1.x; a1.y += v1.y; a1.z += v1.z; a1.w += v1.w;
        a2.x += v2.x; a2.y += v2.y; a2.z += v2.z; a2.w += v2.w;
        a3.x += v3.x; a3.y += v3.y; a3.z += v3.z; a3.w += v3.w;
    }

    // tail window (predicated)
    if (wpos < end) {
        int4 q = __ldg((const int4*)&g_csrc[wpos]);    // pad covers overread
        int rem = end - wpos;                          // 1..3
        {
            float4 v = ((const float4*)(feat + (size_t)q.x * CD))[lane];
            a0.x += v.x; a0.y += v.y; a0.z += v.z; a0.w += v.w;
        }
        if (rem > 1) {
            float4 v = ((const float4*)(feat + (size_t)q.y * CD))[lane];
            a1.x += v.x; a1.y += v.y; a1.z += v.z; a1.w += v.w;
        }
        if (rem > 2) {
            float4 v = ((const float4*)(feat + (size_t)q.z * CD))[lane];
            a2.x += v.x; a2.y += v.y; a2.z += v.z; a2.w += v.w;
        }
    }

    float4 acc;
    acc.x = (a0.x + a1.x) + (a2.x + a3.x);
    acc.y = (a0.y + a1.y) + (a2.y + a3.y);
    acc.z = (a0.z + a1.z) + (a2.z + a3.z);
    acc.w = (a0.w + a1.w) + (a2.w + a3.w);
    float inv = 1.0f / fmaxf((float)deg, 1.0f);
    acc.x *= inv; acc.y *= inv; acc.z *= inv; acc.w *= inv;
    ((float4*)(g_agg + (size_t)w * CD))[lane] = acc;
}

// ---------------- fused agg@Wl + root@Wr + bias GEMM, with global sum/sumsq ----------------
// BM=64 rows x 128 cols per tile; 256 threads: tx(0..15)->8 cols, ty(0..15)->4 rows.
// Dynamic work-stealing (global ticket), row-major A tiles (stride 132,
// conflict-free STS / broadcast LDS.128), register prefetch of the next tile,
// packed fma.rn.f32x2 mainloop with W read from smem as pre-packed ulonglong2.
__global__ void __launch_bounds__(256, 1)
k_gemm(const float* __restrict__ rootExt,
       const float* __restrict__ Wl, const float* __restrict__ bl,
       const float* __restrict__ Wr, int so)
{
    extern __shared__ float smem[];
    float* Wls = smem;                   // 128*128
    float* Wrs = Wls + CD * CD;          // 128*128
    float* Aa  = Wrs + CD * CD;          // [64][AST] row-major mean-agg
    float* Ax  = Aa + BM * AST;          // [64][AST] row-major root
    float* Red = Ax + BM * AST;          // 64 floats reduction scratch
    __shared__ int s_tn;

    const float* root = rootExt ? rootExt : g_h;
    float* out = g_h;

    const int tid = threadIdx.x;
    const int tx = tid & 15, ty = tid >> 4;

    for (int i = tid; i < CD * CD; i += 256) { Wls[i] = Wl[i]; Wrs[i] = Wr[i]; }

    float bias[8];
    *(float4*)&bias[0] = *(const float4*)&bl[tx * 8];
    *(float4*)&bias[4] = *(const float4*)&bl[tx * 8 + 4];

    float s1 = 0.f, s2 = 0.f;
    float4 pva[8], pvx[8];

    // pop first tile + prefetch it
    if (tid == 0) s_tn = atomicAdd(&g_ticket, 1);
    __syncthreads();                     // publishes s_tn; drains W STS
    int t = s_tn;
    if (t < TILES) {
        int row0 = t * BM;
        #pragma unroll
        for (int u = 0; u < 8; ++u) {
            int i = tid + u * 256;
            int r = i >> 5, kq = i & 31;
            int row = row0 + r;
            pva[u] = make_float4(0.f, 0.f, 0.f, 0.f); pvx[u] = pva[u];
            if (row < NN) {
                pva[u] = ((const float4*)(g_agg + (size_t)row * CD))[kq];
                pvx[u] = ((const float4*)(root  + (size_t)row * CD))[kq];
            }
        }
    }

    while (t < TILES) {
        const int row0 = t * BM;
        __syncthreads();   // WAR fence: previous tile's compute done
        #pragma unroll
        for (int u = 0; u < 8; ++u) {
            int i = tid + u * 256;
            int r = i >> 5, kq = i & 31;
            *(float4*)&Aa[r * AST + kq * 4] = pva[u];
            *(float4*)&Ax[r * AST + kq * 4] = pvx[u];
        }
        if (tid == 0) s_tn = atomicAdd(&g_ticket, 1);
        __syncthreads();   // smem A ready AND s_tn published
        const int tn = s_tn;

        // issue next tile's loads now; consumed ~16K cycles later
        if (tn < TILES) {
            int nrow0 = tn * BM;
            #pragma unroll
            for (int u = 0; u < 8; ++u) {
                int i = tid + u * 256;
                int r = i >> 5, kq = i & 31;
                int row = nrow0 + r;
                pva[u] = make_float4(0.f, 0.f, 0.f, 0.f); pvx[u] = pva[u];
                if (row < NN) {
                    pva[u] = ((const float4*)(g_agg + (size_t)row * CD))[kq];
                    pvx[u] = ((const float4*)(root  + (size_t)row * CD))[kq];
                }
            }
        }

        unsigned long long acc[4][4];
        #pragma unroll
        for (int i = 0; i < 4; ++i)
            #pragma unroll
            for (int j = 0; j < 4; ++j) acc[i][j] = 0ull;

        #pragma unroll 2
        for (int k0 = 0; k0 < CD; k0 += 4) {
            float avs[4][4], xvs[4][4];
            #pragma unroll
            for (int i = 0; i < 4; ++i) {
                int row = ty * 4 + i;
                float4 aq = *(const float4*)&Aa[row * AST + k0];
                float4 xq = *(const float4*)&Ax[row * AST + k0];
                avs[i][0] = aq.x; avs[i][1] = aq.y; avs[i][2] = aq.z; avs[i][3] = aq.w;
                xvs[i][0] = xq.x; xvs[i][1] = xq.y; xvs[i][2] = xq.z; xvs[i][3] = xq.w;
            }
            #pragma unroll
            for (int kk = 0; kk < 4; ++kk) {
                const int k = k0 + kk;
                const ulonglong2* wl = (const ulonglong2*)&Wls[(k << 7) + (tx << 3)];
                ulonglong2 L0 = wl[0], L1 = wl[1];
                const ulonglong2* wr = (const ulonglong2*)&Wrs[(k << 7) + (tx << 3)];
                ulonglong2 R0 = wr[0], R1 = wr[1];
                unsigned long long lw[4] = { L0.x, L0.y, L1.x, L1.y };
                unsigned long long rw[4] = { R0.x, R0.y, R1.x, R1.y };
                #pragma unroll
                for (int i = 0; i < 4; ++i) {
                    unsigned long long aa = pk2(avs[i][kk], avs[i][kk]);
                    unsigned long long xx = pk2(xvs[i][kk], xvs[i][kk]);
                    #pragma unroll
                    for (int j = 0; j < 4; ++j) {
                        fma2(acc[i][j], lw[j], aa);
                        fma2(acc[i][j], rw[j], xx);
                    }
                }
            }
        }

        #pragma unroll
        for (int i = 0; i < 4; ++i) {
            int row = row0 + ty * 4 + i;
            if (row < NN) {
                float o[8];
                #pragma unroll
                for (int j = 0; j < 4; ++j)
                    upk2(acc[i][j], o[2*j], o[2*j + 1]);
                #pragma unroll
                for (int j = 0; j < 8; ++j) {
                    float v = o[j] + bias[j];
                    o[j] = v; s1 += v; s2 += v * v;
                }
                float4* op = (float4*)(out + (size_t)row * CD + tx * 8);
                op[0] = make_float4(o[0], o[1], o[2], o[3]);
                op[1] = make_float4(o[4], o[5], o[6], o[7]);
            }
        }
        t = tn;
    }

    // block reduction of (s1, s2) -> one atomicAdd pair per block
    #pragma unroll
    for (int off = 16; off; off >>= 1) {
        s1 += __shfl_xor_sync(0xffffffffu, s1, off);
        s2 += __shfl_xor_sync(0xffffffffu, s2, off);
    }
    __syncthreads();
    if ((tid & 31) == 0) { Red[tid >> 5] = s1; Red[8 + (tid >> 5)] = s2; }
    __syncthreads();
    if (tid == 0) {
        float a = 0.f, b = 0.f;
        for (int w = 0; w < 8; ++w) { a += Red[w]; b += Red[8 + w]; }
        atomicAdd(&g_stats[so], a);
        atomicAdd(&g_stats[so + 1], b);
    }
}

// ---------------- global LayerNorm apply + ReLU (+ optional residual -> out) ----------------
// Affine folded: y = relu(v*A + B), A = sc*gamma, B = beta - mu*sc*gamma.
__global__ void k_ln(const float* __restrict__ g, const float* __restrict__ b,
                     const float* __restrict__ res, float* __restrict__ outExt, int so)
{
    int i = blockIdx.x * blockDim.x + threadIdx.x;
    const int n4 = NN * (CD / 4);
    if (i >= n4) return;
    const float inv = 1.0f / (float)((long long)NN * CD);
    float mu  = g_stats[so] * inv;
    float var = g_stats[so + 1] * inv - mu * mu;
    float sc  = rsqrtf(var + 1e-5f);
    int c4 = i & 31;
    float4 gv = ((const float4*)g)[c4];
    float4 bv = ((const float4*)b)[c4];
    float4 A, B;
    A.x = sc * gv.x; B.x = bv.x - mu * A.x;
    A.y = sc * gv.y; B.y = bv.y - mu * A.y;
    A.z = sc * gv.z; B.z = bv.z - mu * A.z;
    A.w = sc * gv.w; B.w = bv.w - mu * A.w;
    float4 v = ((float4*)g_h)[i];
    float4 o;
    o.x = fmaxf(fmaf(v.x, A.x, B.x), 0.f);
    o.y = fmaxf(fmaf(v.y, A.y, B.y), 0.f);
    o.z = fmaxf(fmaf(v.z, A.z, B.z), 0.f);
    o.w = fmaxf(fmaf(v.w, A.w, B.w), 0.f);
    if (res) {
        float4 rv = ((const float4*)res)[i];
        o.x += rv.x; o.y += rv.y; o.z += rv.z; o.w += rv.w;
        ((float4*)outExt)[i] = o;
    } else {
        ((float4*)g_h)[i] = o;
    }
}

extern "C" void kernel_launch(void* const* d_in, const int* in_sizes, int n_in,
                              void* d_out, int out_size) {
    const float* x   = (const float*)d_in[0];
    const void*  ei  = d_in[1];
    const float* Wl1 = (const float*)d_in[2];
    const float* bl1 = (const float*)d_in[3];
    const float* Wr1 = (const float*)d_in[4];
    const float* g1  = (const float*)d_in[5];
    const float* b1  = (const float*)d_in[6];
    const float* Wl2 = (const float*)d_in[7];
    const float* bl2 = (const float*)d_in[8];
    const float* Wr2 = (const float*)d_in[9];
    const float* g2  = (const float*)d_in[10];
    const float* b2  = (const float*)d_in[11];
    float* out = (float*)d_out;

    cudaFuncSetAttribute(k_gemm, cudaFuncAttributeMaxDynamicSharedMemorySize, SMEM_BYTES);

    const int n4 = NN * (CD / 4);
    const int lgrid = (n4 + 255) / 256;
    const int egrid = (NE + 255) / 256;
    const int agrid = (NN * 32 + 255) / 256;

    // CSR build (rebuilt every call for determinism; reused by both layers)
    k_init<<<SCAN_BLKS, 256>>>((const long long*)ei);
    k_count<<<egrid, 256>>>(ei);
    k_scan1<<<SCAN_BLKS, 256>>>();
    k_scan2<<<1, 512>>>();
    k_scan3<<<SCAN_BLKS, 256>>>();
    k_fill<<<egrid, 256>>>(ei);

    // layer 1
    k_agg<<<agrid, 256>>>(x);                                      // also resets ticket
    k_gemm<<<148, 256, SMEM_BYTES>>>(x, Wl1, bl1, Wr1, 0);
    k_ln<<<lgrid, 256>>>(g1, b1, nullptr, nullptr, 0);

    // layer 2
    k_agg<<<agrid, 256>>>(nullptr);                                // feat = g_h; resets ticket
    k_gemm<<<148, 256, SMEM_BYTES>>>(nullptr, Wl2, bl2, Wr2, 2);   // root = g_h, in-place
    k_ln<<<lgrid, 256>>>(g2, b2, x, out, 2);
}

// round 17
// speedup vs baseline: 1.5078x; 1.5078x over previous
#include <cuda_runtime.h>
#include <cstdint>

#define NN 100000
#define NE 1600000
#define CD 128

static const int BM = 64;
static const int TILES = (NN + BM - 1) / BM;   // 1563
static const int AST = 132;                    // row-major A stride (4r+k bank spread)
static const int SMEM_FLOATS = (CD*CD*2 + BM*AST*2 + 64);
static const int SMEM_BYTES = SMEM_FLOATS * 4; // 198912 bytes
static const int SCAN_BLKS = (NN + 255) / 256; // 391

// ---- scratch (device globals: allocation-free rule; zero-initialized at load) ----
__device__ float g_agg[(size_t)NN * CD];
__device__ float g_h[(size_t)NN * CD];
__device__ int   g_csrc[NE + 8];               // +8 pad: aligned-window overread safety
__device__ int   g_rowptr[NN];
__device__ int   g_cursor[NN];
__device__ int   g_cnt[NN];
__device__ unsigned long long g_state[SCAN_BLKS]; // scan: (flag<<62)|value, flag 1=agg,2=pfx
__device__ float g_stats[4];
__device__ int   g_ticket;

// ---------------- packed f32x2 helpers ----------------
__device__ __forceinline__ unsigned long long pk2(float lo, float hi) {
    unsigned long long r;
    asm("mov.b64 %0, {%1, %2};" : "=l"(r) : "f"(lo), "f"(hi));
    return r;
}
__device__ __forceinline__ void fma2(unsigned long long& d,
                                     unsigned long long a, unsigned long long b) {
    asm("fma.rn.f32x2 %0, %1, %2, %0;" : "+l"(d) : "l"(a), "l"(b));
}
__device__ __forceinline__ void upk2(unsigned long long v, float& lo, float& hi) {
    asm("mov.b64 {%0, %1}, %2;" : "=f"(lo), "=f"(hi) : "l"(v));
}

// int64-vs-int32 edge dtype detection, per-block (shared broadcast).
// int32 data read as int64 carries a node-id in the high word -> >= NN w.h.p.
__device__ __forceinline__ int detect_is64_block(const void* eiv, int* s_flag) {
    if (threadIdx.x == 0) {
        const long long* e = (const long long*)eiv;
        int ok = 1;
        for (int j = 0; j < 16; ++j)
            if ((unsigned long long)e[j] >= (unsigned long long)NN) ok = 0;
        *s_flag = ok;
    }
    __syncthreads();
    return *s_flag;
}

// ---------------- in-degree count ----------------
__global__ void k_count(const void* __restrict__ eiv) {
    __shared__ int s_is64;
    int is64 = detect_is64_block(eiv, &s_is64);
    int i = blockIdx.x * blockDim.x + threadIdx.x;
    if (i >= NE) return;
    int d;
    if (is64) d = (int)((const long long*)eiv)[NE + i];
    else      d = ((const int*)eiv)[NE + i];
    atomicAdd(&g_cnt[d], 1);
}

// ---------------- single-pass CSR scan (decoupled lookback) ----------------
__device__ __forceinline__ int scan_lookback(int b) {
    int lane = threadIdx.x & 31;
    int run = 0;
    int tail = b;
    while (tail > 0) {
        int j = tail - 1 - lane;          // lane 0 reads the closest predecessor
        unsigned long long st = 0ull;
        if (j >= 0) {
            do { st = ((volatile unsigned long long*)g_state)[j]; } while ((st >> 62) == 0ull);
        }
        int flag = (int)(st >> 62);
        int val  = (int)(st & 0xffffffffull);
        unsigned pm = __ballot_sync(0xffffffffu, (j >= 0) && (flag == 2));
        if (pm) {
            int closest = __ffs(pm) - 1;   // smallest lane = largest j with a prefix
            int c = (j >= 0 && lane <= closest) ? val : 0;
            #pragma unroll
            for (int o = 16; o; o >>= 1) c += __shfl_xor_sync(0xffffffffu, c, o);
            run += c;
            return run;
        }
        int c = (j >= 0) ? val : 0;
        #pragma unroll
        for (int o = 16; o; o >>= 1) c += __shfl_xor_sync(0xffffffffu, c, o);
        run += c;
        tail -= 32;
    }
    return run;
}

__global__ void k_scan() {
    __shared__ int s[256];
    __shared__ int base_sh;
    int b = blockIdx.x, tid = threadIdx.x;
    int i = b * 256 + tid;
    int v = (i < NN) ? g_cnt[i] : 0;
    s[tid] = v;
    __syncthreads();
    #pragma unroll
    for (int off = 1; off < 256; off <<= 1) {
        int t = (tid >= off) ? s[tid - off] : 0;
        __syncthreads();
        s[tid] += t;
        __syncthreads();
    }
    int excl = s[tid] - v;                 // block-local exclusive
    int aggB = s[255];                     // block aggregate
    if (tid == 0) {                        // publish aggregate (flag=1)
        ((volatile unsigned long long*)g_state)[b] =
            (1ull << 62) | (unsigned long long)(unsigned)aggB;
    }
    if (tid < 32) {
        int run = scan_lookback(b);        // exclusive prefix of this block
        if (tid == 0) {
            ((volatile unsigned long long*)g_state)[b] =
                (2ull << 62) | (unsigned long long)(unsigned)(run + aggB);
            base_sh = run;
        }
    }
    __syncthreads();
    if (i < NN) {
        int r = excl + base_sh;
        g_rowptr[i] = r;
        g_cursor[i] = r;
    }
}

// ---------------- CSR fill ----------------
__global__ void k_fill(const void* __restrict__ eiv) {
    __shared__ int s_is64;
    int is64 = detect_is64_block(eiv, &s_is64);
    int i = blockIdx.x * blockDim.x + threadIdx.x;
    if (i >= NE) return;
    int s, d;
    if (is64) {
        const long long* ei = (const long long*)eiv;
        s = (int)ei[i]; d = (int)ei[NE + i];
    } else {
        const int* ei = (const int*)eiv;
        s = ei[i]; d = ei[NE + i];
    }
    int pos = atomicAdd(&g_cursor[d], 1);
    g_csrc[pos] = s;
}

// ---------------- pull-side mean aggregation: one warp per dst node ----------------
// Aligned int4 index windows. Head/tail windows carry predicates; interior
// windows are guard-free and unrolled x2 (up to 10 loads in flight/warp).
// Also resets the GEMM work-stealing ticket (stream-ordered before each k_gemm).
__global__ void k_agg(const float* __restrict__ featExt) {
    if (blockIdx.x == 0 && threadIdx.x == 0) g_ticket = 0;
    int w = (blockIdx.x * blockDim.x + threadIdx.x) >> 5;
    int lane = threadIdx.x & 31;
    if (w >= NN) return;
    const float* feat = featExt ? featExt : g_h;
    const int base = g_rowptr[w];
    const int deg = g_cnt[w];
    const int end = base + deg;

    float4 a0 = make_float4(0.f, 0.f, 0.f, 0.f);
    float4 a1 = a0, a2 = a0, a3 = a0;

    int wpos = base & ~3;

    // head window (predicated) — only if base is misaligned
    if (wpos < base) {
        int4 q = __ldg((const int4*)&g_csrc[wpos]);
        if (wpos + 0 >= base && wpos + 0 < end) {
            float4 v = ((const float4*)(feat + (size_t)q.x * CD))[lane];
            a0.x += v.x; a0.y += v.y; a0.z += v.z; a0.w += v.w;
        }
        if (wpos + 1 >= base && wpos + 1 < end) {
            float4 v = ((const float4*)(feat + (size_t)q.y * CD))[lane];
            a1.x += v.x; a1.y += v.y; a1.z += v.z; a1.w += v.w;
        }
        if (wpos + 2 >= base && wpos + 2 < end) {
            float4 v = ((const float4*)(feat + (size_t)q.z * CD))[lane];
            a2.x += v.x; a2.y += v.y; a2.z += v.z; a2.w += v.w;
        }
        if (wpos + 3 >= base && wpos + 3 < end) {
            float4 v = ((const float4*)(feat + (size_t)q.w * CD))[lane];
            a3.x += v.x; a3.y += v.y; a3.z += v.z; a3.w += v.w;
        }
        wpos += 4;
    }

    // interior windows — fully covered, no guards; unroll x2 for deeper MLP
    #pragma unroll 2
    for (; wpos + 4 <= end; wpos += 4) {
        int4 q = __ldg((const int4*)&g_csrc[wpos]);
        float4 v0 = ((const float4*)(feat + (size_t)q.x * CD))[lane];
        float4 v1 = ((const float4*)(feat + (size_t)q.y * CD))[lane];
        float4 v2 = ((const float4*)(feat + (size_t)q.z * CD))[lane];
        float4 v3 = ((const float4*)(feat + (size_t)q.w * CD))[lane];
        a0.x += v0.x; a0.y += v0.y; a0.z += v0.z; a0.w += v0.w;
        a1.x += v1.x; a1.y += v1.y; a1.z += v1.z; a1.w += v1.w;
        a2.x += v2.x; a2.y += v2.y; a2.z += v2.z; a2.w += v2.w;
        a3.x += v3.x; a3.y += v3.y; a3.z += v3.z; a3.w += v3.w;
    }

    // tail window (predicated)
    if (wpos < end) {
        int4 q = __ldg((const int4*)&g_csrc[wpos]);    // pad covers overread
        int rem = end - wpos;                          // 1..3
        {
            float4 v = ((const float4*)(feat + (size_t)q.x * CD))[lane];
            a0.x += v.x; a0.y += v.y; a0.z += v.z; a0.w += v.w;
        }
        if (rem > 1) {
            float4 v = ((const float4*)(feat + (size_t)q.y * CD))[lane];
            a1.x += v.x; a1.y += v.y; a1.z += v.z; a1.w += v.w;
        }
        if (rem > 2) {
            float4 v = ((const float4*)(feat + (size_t)q.z * CD))[lane];
            a2.x += v.x; a2.y += v.y; a2.z += v.z; a2.w += v.w;
        }
    }

    float4 acc;
    acc.x = (a0.x + a1.x) + (a2.x + a3.x);
    acc.y = (a0.y + a1.y) + (a2.y + a3.y);
    acc.z = (a0.z + a1.z) + (a2.z + a3.z);
    acc.w = (a0.w + a1.w) + (a2.w + a3.w);
    float inv = 1.0f / fmaxf((float)deg, 1.0f);
    acc.x *= inv; acc.y *= inv; acc.z *= inv; acc.w *= inv;
    ((float4*)(g_agg + (size_t)w * CD))[lane] = acc;
}

// ---------------- fused agg@Wl + root@Wr + bias GEMM, with global sum/sumsq ----------------
// BM=64 rows x 128 cols per tile; 256 threads: tx(0..15)->8 cols, ty(0..15)->4 rows.
// Dynamic work-stealing (global ticket), row-major A tiles (stride 132,
// conflict-free STS / broadcast LDS.128), register prefetch of the next tile,
// packed fma.rn.f32x2 mainloop with W read from smem as pre-packed ulonglong2.
__global__ void __launch_bounds__(256, 1)
k_gemm(const float* __restrict__ rootExt,
       const float* __restrict__ Wl, const float* __restrict__ bl,
       const float* __restrict__ Wr, int so)
{
    extern __shared__ float smem[];
    float* Wls = smem;                   // 128*128
    float* Wrs = Wls + CD * CD;          // 128*128
    float* Aa  = Wrs + CD * CD;          // [64][AST] row-major mean-agg
    float* Ax  = Aa + BM * AST;          // [64][AST] row-major root
    float* Red = Ax + BM * AST;          // 64 floats reduction scratch
    __shared__ int s_tn;

    const float* root = rootExt ? rootExt : g_h;
    float* out = g_h;

    const int tid = threadIdx.x;
    const int tx = tid & 15, ty = tid >> 4;

    for (int i = tid; i < CD * CD; i += 256) { Wls[i] = Wl[i]; Wrs[i] = Wr[i]; }

    float bias[8];
    *(float4*)&bias[0] = *(const float4*)&bl[tx * 8];
    *(float4*)&bias[4] = *(const float4*)&bl[tx * 8 + 4];

    float s1 = 0.f, s2 = 0.f;
    float4 pva[8], pvx[8];

    // pop first tile + prefetch it
    if (tid == 0) s_tn = atomicAdd(&g_ticket, 1);
    __syncthreads();                     // publishes s_tn; drains W STS
    int t = s_tn;
    if (t < TILES) {
        int row0 = t * BM;
        #pragma unroll
        for (int u = 0; u < 8; ++u) {
            int i = tid + u * 256;
            int r = i >> 5, kq = i & 31;
            int row = row0 + r;
            pva[u] = make_float4(0.f, 0.f, 0.f, 0.f); pvx[u] = pva[u];
            if (row < NN) {
                pva[u] = ((const float4*)(g_agg + (size_t)row * CD))[kq];
                pvx[u] = ((const float4*)(root  + (size_t)row * CD))[kq];
            }
        }
    }

    while (t < TILES) {
        const int row0 = t * BM;
        __syncthreads();   // WAR fence: previous tile's compute done
        #pragma unroll
        for (int u = 0; u < 8; ++u) {
            int i = tid + u * 256;
            int r = i >> 5, kq = i & 31;
            *(float4*)&Aa[r * AST + kq * 4] = pva[u];
            *(float4*)&Ax[r * AST + kq * 4] = pvx[u];
        }
        if (tid == 0) s_tn = atomicAdd(&g_ticket, 1);
        __syncthreads();   // smem A ready AND s_tn published
        const int tn = s_tn;

        // issue next tile's loads now; consumed ~16K cycles later
        if (tn < TILES) {
            int nrow0 = tn * BM;
            #pragma unroll
            for (int u = 0; u < 8; ++u) {
                int i = tid + u * 256;
                int r = i >> 5, kq = i & 31;
                int row = nrow0 + r;
                pva[u] = make_float4(0.f, 0.f, 0.f, 0.f); pvx[u] = pva[u];
                if (row < NN) {
                    pva[u] = ((const float4*)(g_agg + (size_t)row * CD))[kq];
                    pvx[u] = ((const float4*)(root  + (size_t)row * CD))[kq];
                }
            }
        }

        unsigned long long acc[4][4];
        #pragma unroll
        for (int i = 0; i < 4; ++i)
            #pragma unroll
            for (int j = 0; j < 4; ++j) acc[i][j] = 0ull;

        #pragma unroll 2
        for (int k0 = 0; k0 < CD; k0 += 4) {
            float avs[4][4], xvs[4][4];
            #pragma unroll
            for (int i = 0; i < 4; ++i) {
                int row = ty * 4 + i;
                float4 aq = *(const float4*)&Aa[row * AST + k0];
                float4 xq = *(const float4*)&Ax[row * AST + k0];
                avs[i][0] = aq.x; avs[i][1] = aq.y; avs[i][2] = aq.z; avs[i][3] = aq.w;
                xvs[i][0] = xq.x; xvs[i][1] = xq.y; xvs[i][2] = xq.z; xvs[i][3] = xq.w;
            }
            #pragma unroll
            for (int kk = 0; kk < 4; ++kk) {
                const int k = k0 + kk;
                const ulonglong2* wl = (const ulonglong2*)&Wls[(k << 7) + (tx << 3)];
                ulonglong2 L0 = wl[0], L1 = wl[1];
                const ulonglong2* wr = (const ulonglong2*)&Wrs[(k << 7) + (tx << 3)];
                ulonglong2 R0 = wr[0], R1 = wr[1];
                unsigned long long lw[4] = { L0.x, L0.y, L1.x, L1.y };
                unsigned long long rw[4] = { R0.x, R0.y, R1.x, R1.y };
                #pragma unroll
                for (int i = 0; i < 4; ++i) {
                    unsigned long long aa = pk2(avs[i][kk], avs[i][kk]);
                    unsigned long long xx = pk2(xvs[i][kk], xvs[i][kk]);
                    #pragma unroll
                    for (int j = 0; j < 4; ++j) {
                        fma2(acc[i][j], lw[j], aa);
                        fma2(acc[i][j], rw[j], xx);
                    }
                }
            }
        }

        #pragma unroll
        for (int i = 0; i < 4; ++i) {
            int row = row0 + ty * 4 + i;
            if (row < NN) {
                float o[8];
                #pragma unroll
                for (int j = 0; j < 4; ++j)
                    upk2(acc[i][j], o[2*j], o[2*j + 1]);
                #pragma unroll
                for (int j = 0; j < 8; ++j) {
                    float v = o[j] + bias[j];
                    o[j] = v; s1 += v; s2 += v * v;
                }
                float4* op = (float4*)(out + (size_t)row * CD + tx * 8);
                op[0] = make_float4(o[0], o[1], o[2], o[3]);
                op[1] = make_float4(o[4], o[5], o[6], o[7]);
            }
        }
        t = tn;
    }

    // block reduction of (s1, s2) -> one atomicAdd pair per block
    #pragma unroll
    for (int off = 16; off; off >>= 1) {
        s1 += __shfl_xor_sync(0xffffffffu, s1, off);
        s2 += __shfl_xor_sync(0xffffffffu, s2, off);
    }
    __syncthreads();
    if ((tid & 31) == 0) { Red[tid >> 5] = s1; Red[8 + (tid >> 5)] = s2; }
    __syncthreads();
    if (tid == 0) {
        float a = 0.f, b = 0.f;
        for (int w = 0; w < 8; ++w) { a += Red[w]; b += Red[8 + w]; }
        atomicAdd(&g_stats[so], a);
        atomicAdd(&g_stats[so + 1], b);
    }
}

// ---------------- global LayerNorm apply + ReLU (+ optional residual -> out) ----------------
// Affine folded: y = relu(v*A + B), A = sc*gamma, B = beta - mu*sc*gamma.
__global__ void k_ln(const float* __restrict__ g, const float* __restrict__ b,
                     const float* __restrict__ res, float* __restrict__ outExt, int so)
{
    int i = blockIdx.x * blockDim.x + threadIdx.x;
    const int n4 = NN * (CD / 4);
    if (i >= n4) return;
    const float inv = 1.0f / (float)((long long)NN * CD);
    float mu  = g_stats[so] * inv;
    float var = g_stats[so + 1] * inv - mu * mu;
    float sc  = rsqrtf(var + 1e-5f);
    int c4 = i & 31;
    float4 gv = ((const float4*)g)[c4];
    float4 bv = ((const float4*)b)[c4];
    float4 A, B;
    A.x = sc * gv.x; B.x = bv.x - mu * A.x;
    A.y = sc * gv.y; B.y = bv.y - mu * A.y;
    A.z = sc * gv.z; B.z = bv.z - mu * A.z;
    A.w = sc * gv.w; B.w = bv.w - mu * A.w;
    float4 v = ((float4*)g_h)[i];
    float4 o;
    o.x = fmaxf(fmaf(v.x, A.x, B.x), 0.f);
    o.y = fmaxf(fmaf(v.y, A.y, B.y), 0.f);
    o.z = fmaxf(fmaf(v.z, A.z, B.z), 0.f);
    o.w = fmaxf(fmaf(v.w, A.w, B.w), 0.f);
    if (res) {
        float4 rv = ((const float4*)res)[i];
        o.x += rv.x; o.y += rv.y; o.z += rv.z; o.w += rv.w;
        ((float4*)outExt)[i] = o;
    } else {
        ((float4*)g_h)[i] = o;
    }
}

// ---------------- trailing cleanup: restore zeroed state for the next call ----------------
__global__ void k_cleanup() {
    int i = blockIdx.x * blockDim.x + threadIdx.x;
    if (i < NN) g_cnt[i] = 0;
    if (i < SCAN_BLKS) g_state[i] = 0ull;
    if (i < 4) g_stats[i] = 0.f;
}

extern "C" void kernel_launch(void* const* d_in, const int* in_sizes, int n_in,
                              void* d_out, int out_size) {
    const float* x   = (const float*)d_in[0];
    const void*  ei  = d_in[1];
    const float* Wl1 = (const float*)d_in[2];
    const float* bl1 = (const float*)d_in[3];
    const float* Wr1 = (const float*)d_in[4];
    const float* g1  = (const float*)d_in[5];
    const float* b1  = (const float*)d_in[6];
    const float* Wl2 = (const float*)d_in[7];
    const float* bl2 = (const float*)d_in[8];
    const float* Wr2 = (const float*)d_in[9];
    const float* g2  = (const float*)d_in[10];
    const float* b2  = (const float*)d_in[11];
    float* out = (float*)d_out;

    cudaFuncSetAttribute(k_gemm, cudaFuncAttributeMaxDynamicSharedMemorySize, SMEM_BYTES);

    const int n4 = NN * (CD / 4);
    const int lgrid = (n4 + 255) / 256;
    const int egrid = (NE + 255) / 256;
    const int agrid = (NN * 32 + 255) / 256;

    // CSR build (g_cnt/g_state/g_stats are zero: static zero-init on first call,
    // k_cleanup on subsequent calls — identical state and work every call)
    k_count<<<egrid, 256>>>(ei);            // idx 0
    k_scan<<<SCAN_BLKS, 256>>>();           // idx 1  (single-pass decoupled lookback)
    k_fill<<<egrid, 256>>>(ei);             // idx 2

    // layer 1
    k_agg<<<agrid, 256>>>(x);               // idx 3  <- ncu capture slot
    k_gemm<<<148, 256, SMEM_BYTES>>>(x, Wl1, bl1, Wr1, 0);      // idx 4
    k_ln<<<lgrid, 256>>>(g1, b1, nullptr, nullptr, 0);          // idx 5

    // layer 2
    k_agg<<<agrid, 256>>>(nullptr);                             // idx 6
    k_gemm<<<148, 256, SMEM_BYTES>>>(nullptr, Wl2, bl2, Wr2, 2);// idx 7
    k_ln<<<lgrid, 256>>>(g2, b2, x, out, 2);                    // idx 8

    k_cleanup<<<SCAN_BLKS, 256>>>();        // idx 9: re-zero state for next call
}